// round 2
// baseline (speedup 1.0000x reference)
#include <cuda_runtime.h>
#include <cuda_bf16.h>

// Problem shapes (fixed by the reference):
//   query_times [B,P,LE]  (d_in[0])
//   event_times [B,P,L]   (d_in[1], sorted along L)
//   mu          [B,M,P,L] (d_in[2])
//   alpha       [B,M,P,L] (d_in[3])
//   beta        [B,M,P,L] (d_in[4])
//   out         [B,M,P,LE] fp32
constexpr int B  = 8;
constexpr int P  = 16;
constexpr int L  = 256;
constexpr int M  = 16;
constexpr int LE = 2048;

constexpr int TPB    = 256;
constexpr int CHUNKS = LE / TPB;   // 8 chunks per (b,p)

__global__ __launch_bounds__(TPB)
void hawkes_kernel(const float* __restrict__ q,
                   const float* __restrict__ ev,
                   const float* __restrict__ mu,
                   const float* __restrict__ al,
                   const float* __restrict__ be,
                   float* __restrict__ out)
{
    __shared__ float sev[L];

    const int blk = blockIdx.x;        // b*P*CHUNKS + p*CHUNKS + c
    const int c   = blk % CHUNKS;
    const int bp  = blk / CHUNKS;      // b*P + p
    const int p   = bp % P;
    const int b   = bp / P;

    // Stage event times for this (b,p) into shared (1 KB).
    sev[threadIdx.x] = ev[bp * L + threadIdx.x];
    __syncthreads();

    const int   le = c * TPB + threadIdx.x;
    const float qt = q[bp * LE + le];

    // Lower bound: lo = number of events strictly < qt.
    // 257 possible outcomes -> need 9 iterations, not 8.
    int lo = 0, hi = L;
    #pragma unroll
    for (int it = 0; it < 9; ++it) {
        if (lo < hi) {
            int mid = (lo + hi) >> 1;
            if (sev[mid] < qt) lo = mid + 1; else hi = mid;
        }
    }
    const int   last = lo - 1;
    const int   ci   = (last < 0) ? 0   : last;
    const float tl   = (last < 0) ? 0.f : sev[ci];
    const float dt   = qt - tl;

    // Gather base pointers: params laid out [B,M,P,L]; m-stride = P*L.
    const int pstride = P * L;
    const float* mup = mu + ((size_t)(b * M) * P + p) * L + ci;
    const float* alp = al + ((size_t)(b * M) * P + p) * L + ci;
    const float* bep = be + ((size_t)(b * M) * P + p) * L + ci;

    // Output: [B,M,P,LE]; m-stride = P*LE. Coalesced across le within a warp.
    const size_t ostride = (size_t)P * LE;
    float* op = out + ((size_t)(b * M) * P + p) * LE + le;

    #pragma unroll
    for (int m = 0; m < M; ++m) {
        const float mm = __ldg(mup + m * pstride);
        const float aa = __ldg(alp + m * pstride);
        const float bb = __ldg(bep + m * pstride);
        const float e    = __expf(-bb * dt);
        const float base = fmaf(aa - mm, e, mm);           // mu + (alpha-mu)*e
        // base in (0,1) here (convex combo of mu,alpha in [0,1)), so the
        // naive fast softplus is numerically safe: arg of log in [2, 3.72].
        op[(size_t)m * ostride] = __logf(1.0f + __expf(base));
    }
}

extern "C" void kernel_launch(void* const* d_in, const int* in_sizes, int n_in,
                              void* d_out, int out_size)
{
    const float* q  = (const float*)d_in[0];
    const float* ev = (const float*)d_in[1];
    const float* mu = (const float*)d_in[2];
    const float* al = (const float*)d_in[3];
    const float* be = (const float*)d_in[4];
    float* out = (float*)d_out;

    dim3 grid(B * P * CHUNKS);   // 1024 blocks
    dim3 block(TPB);
    hawkes_kernel<<<grid, block>>>(q, ev, mu, al, be, out);
}